// round 1
// baseline (speedup 1.0000x reference)
#include <cuda_runtime.h>

#define D 4096
#define S_SEG 128
#define NROWS (S_SEG * 15)   // 1920

#define BM 128
#define BN 128
#define BK 16
#define TM 8
#define TN 8

__constant__ float c_nodes[15] = {
    0.20778495500789848f,  0.4058451513773972f,  0.5860872354676911f,
    0.7415311855993945f,   0.8648644233597691f,  0.9491079123427585f,
    0.9914553711208126f,  -0.9914553711208126f, -0.9491079123427585f,
   -0.8648644233597691f,  -0.7415311855993945f, -0.5860872354676911f,
   -0.4058451513773972f,  -0.20778495500789848f, 0.0f
};
__constant__ float c_wk[15] = {
    0.20443294007529889f, 0.19035057806478542f, 0.1690047266392679f,
    0.14065325971552592f, 0.10479001032225019f, 0.06309209262997856f,
    0.022935322010529224f, 0.022935322010529224f, 0.06309209262997856f,
    0.10479001032225019f, 0.14065325971552592f, 0.1690047266392679f,
    0.19035057806478542f, 0.20443294007529889f, 0.20948214108472782f
};

// Scratch (allocation-free rule: __device__ globals)
__device__ float g_phi[(size_t)NROWS * D];
__device__ float g_g[(size_t)NROWS * D];

__device__ __forceinline__ float row_t(int m) {
    int s = m / 15;
    int i = m - s * 15;
    // t = c + h*node, c=(2s+1)/256 (exact in fp32), h=1/256
    return fmaf(c_nodes[i], 1.0f / 256.0f, (float)(2 * s + 1) * (1.0f / 256.0f));
}
__device__ __forceinline__ float row_coef(int m) {
    int i = m % 15;
    return c_wk[i] * (1.0f / 256.0f);
}

// K1: phi[m][d] = sin(t_m * freqs[d]); float4 per thread
__global__ __launch_bounds__(256) void phi_kernel(const float* __restrict__ freqs) {
    int idx = blockIdx.x * blockDim.x + threadIdx.x;   // NROWS*1024 threads
    int m  = idx >> 10;          // D/4 = 1024 quads per row
    int d4 = (idx & 1023) << 2;
    float t = row_t(m);
    float4 f = *reinterpret_cast<const float4*>(freqs + d4);
    float4 o;
    o.x = sinf(t * f.x);
    o.y = sinf(t * f.y);
    o.z = sinf(t * f.z);
    o.w = sinf(t * f.w);
    *reinterpret_cast<float4*>(g_phi + (size_t)m * D + d4) = o;
}

// K2: z = phi @ W (+b), then g = coef * cos(t*afreq) * (1 - tanh(z)^2)
// A = phi [NROWS, D] row-major (needs transpose into smem), B = W [D, D]
__global__ __launch_bounds__(256) void gemm1_kernel(const float* __restrict__ W,
                                                    const float* __restrict__ bias,
                                                    const float* __restrict__ afreqs) {
    __shared__ float As[BK][BM + 4];   // +4 pad: conflict-free transposed stores, keeps 16B alignment (132*4=528)
    __shared__ float Bs[BK][BN];

    const int bm = blockIdx.y * BM;    // row tile base (0..1792)
    const int bn = blockIdx.x * BN;    // col tile base
    const int tid = threadIdx.x;
    const int tx = tid & 15;           // 16 col-threads
    const int ty = tid >> 4;           // 16 row-threads

    float acc[TM][TN] = {};

    // A loader: 128 rows x 16 cols; thread -> (row = tid/4 [+64], col4 = (tid%4)*4)
    const int arow = tid >> 2;
    const int acol = (tid & 3) << 2;
    // B loader: 16 rows x 128 cols; thread -> (row = tid/32 [+8], col4 = (tid%32)*4)
    const int brow = tid >> 5;
    const int bcol = (tid & 31) << 2;

    const float* Abase = g_phi + (size_t)bm * D;

    for (int k0 = 0; k0 < D; k0 += BK) {
        #pragma unroll
        for (int it = 0; it < 2; it++) {
            int r = arow + it * 64;
            float4 v = *reinterpret_cast<const float4*>(Abase + (size_t)r * D + k0 + acol);
            As[acol + 0][r] = v.x;
            As[acol + 1][r] = v.y;
            As[acol + 2][r] = v.z;
            As[acol + 3][r] = v.w;
        }
        #pragma unroll
        for (int it = 0; it < 2; it++) {
            int r = brow + it * 8;
            float4 v = *reinterpret_cast<const float4*>(W + (size_t)(k0 + r) * D + bn + bcol);
            *reinterpret_cast<float4*>(&Bs[r][bcol]) = v;
        }
        __syncthreads();

        #pragma unroll
        for (int k = 0; k < BK; k++) {
            float a[TM], bb[TN];
            #pragma unroll
            for (int i = 0; i < TM; i++) a[i] = As[k][ty * TM + i];
            #pragma unroll
            for (int j = 0; j < TN; j++) bb[j] = Bs[k][tx * TN + j];
            #pragma unroll
            for (int i = 0; i < TM; i++)
                #pragma unroll
                for (int j = 0; j < TN; j++)
                    acc[i][j] = fmaf(a[i], bb[j], acc[i][j]);
        }
        __syncthreads();
    }

    // Epilogue: fused bias + tanh + cos weighting
    #pragma unroll
    for (int i = 0; i < TM; i++) {
        int m = bm + ty * TM + i;
        float t = row_t(m);
        float coef = row_coef(m);
        float* orow = g_g + (size_t)m * D + bn + tx * TN;
        #pragma unroll
        for (int j4 = 0; j4 < TN; j4 += 4) {
            float4 o;
            float r[4];
            #pragma unroll
            for (int j = 0; j < 4; j++) {
                int n = bn + tx * TN + j4 + j;
                float z = acc[i][j4 + j] + bias[n];
                float y = tanhf(z);
                r[j] = coef * cosf(t * afreqs[n]) * (1.0f - y * y);
            }
            o.x = r[0]; o.y = r[1]; o.z = r[2]; o.w = r[3];
            *reinterpret_cast<float4*>(orow + j4) = o;
        }
    }
}

// K3: out = phi^T @ g : out[i][j] = sum_n phi[n][i]*g[n][j]
// Both operands K-major (n is the reduction dim, contiguous rows) -> direct smem loads, no transpose
__global__ __launch_bounds__(256) void gemm2_kernel(float* __restrict__ out) {
    __shared__ float As[BK][BM];
    __shared__ float Bs[BK][BN];

    const int bi = blockIdx.y * BM;    // output row tile (phi column)
    const int bj = blockIdx.x * BN;    // output col tile (g column)
    const int tid = threadIdx.x;
    const int tx = tid & 15;
    const int ty = tid >> 4;

    float acc[TM][TN] = {};

    const int lrow = tid >> 5;         // 0..7, two iters -> 16 rows
    const int lcol = (tid & 31) << 2;  // 0..124 step 4

    for (int k0 = 0; k0 < NROWS; k0 += BK) {
        #pragma unroll
        for (int it = 0; it < 2; it++) {
            int r = lrow + it * 8;
            float4 va = *reinterpret_cast<const float4*>(g_phi + (size_t)(k0 + r) * D + bi + lcol);
            *reinterpret_cast<float4*>(&As[r][lcol]) = va;
            float4 vb = *reinterpret_cast<const float4*>(g_g + (size_t)(k0 + r) * D + bj + lcol);
            *reinterpret_cast<float4*>(&Bs[r][lcol]) = vb;
        }
        __syncthreads();

        #pragma unroll
        for (int k = 0; k < BK; k++) {
            float a[TM], bb[TN];
            #pragma unroll
            for (int i = 0; i < TM; i++) a[i] = As[k][ty * TM + i];
            #pragma unroll
            for (int j = 0; j < TN; j++) bb[j] = Bs[k][tx * TN + j];
            #pragma unroll
            for (int i = 0; i < TM; i++)
                #pragma unroll
                for (int j = 0; j < TN; j++)
                    acc[i][j] = fmaf(a[i], bb[j], acc[i][j]);
        }
        __syncthreads();
    }

    #pragma unroll
    for (int i = 0; i < TM; i++) {
        int row = bi + ty * TM + i;
        float* orow = out + (size_t)row * D + bj + tx * TN;
        #pragma unroll
        for (int j4 = 0; j4 < TN; j4 += 4) {
            float4 o;
            o.x = acc[i][j4 + 0];
            o.y = acc[i][j4 + 1];
            o.z = acc[i][j4 + 2];
            o.w = acc[i][j4 + 3];
            *reinterpret_cast<float4*>(orow + j4) = o;
        }
    }
}

extern "C" void kernel_launch(void* const* d_in, const int* in_sizes, int n_in,
                              void* d_out, int out_size) {
    const float* W      = (const float*)d_in[0];
    const float* bias   = (const float*)d_in[1];
    const float* freqs  = (const float*)d_in[2];
    const float* afreqs = (const float*)d_in[3];
    float* out = (float*)d_out;

    // K1: phi (1920*4096 elems, 4 per thread)
    phi_kernel<<<(NROWS * (D / 4)) / 256, 256>>>(freqs);
    // K2: fused GEMM1 + tanh/cos epilogue. Grid: 32 col tiles x 15 row tiles
    gemm1_kernel<<<dim3(D / BN, NROWS / BM), 256>>>(W, bias, afreqs);
    // K3: GEMM2 -> d_out. Grid 32 x 32
    gemm2_kernel<<<dim3(D / BN, D / BM), 256>>>(out);
    (void)in_sizes; (void)n_in; (void)out_size;
}

// round 4
// speedup vs baseline: 3.1488x; 3.1488x over previous
#include <cuda_runtime.h>
#include <cstdint>
#include <cstddef>

#define DD 4096
#define NROWS 1920

#define BM 128
#define BN 128
#define BK 16
#define NSTAGE 4
#define NTHREADS 256

#define ASTRIDE 20            // floats per A smem row (pad 16->20: conflict-free)
#define BSTRIDE 136           // floats per B smem row (pad 128->136: conflict-free)
#define A_STG (BM * ASTRIDE)  // 2560 floats
#define B_STG (BK * BSTRIDE)  // 2176 floats
#define SMEM_FLOATS (NSTAGE * (A_STG + B_STG))
#define SMEM_BYTES  (SMEM_FLOATS * 4)   // 75776

__constant__ float c_nodes[15] = {
    0.20778495500789848f,  0.4058451513773972f,  0.5860872354676911f,
    0.7415311855993945f,   0.8648644233597691f,  0.9491079123427585f,
    0.9914553711208126f,  -0.9914553711208126f, -0.9491079123427585f,
   -0.8648644233597691f,  -0.7415311855993945f, -0.5860872354676911f,
   -0.4058451513773972f,  -0.20778495500789848f, 0.0f
};
__constant__ float c_wk[15] = {
    0.20443294007529889f, 0.19035057806478542f, 0.1690047266392679f,
    0.14065325971552592f, 0.10479001032225019f, 0.06309209262997856f,
    0.022935322010529224f, 0.022935322010529224f, 0.06309209262997856f,
    0.10479001032225019f, 0.14065325971552592f, 0.1690047266392679f,
    0.19035057806478542f, 0.20443294007529889f, 0.20948214108472782f
};

// Scratch (__device__ globals: allocation-free rule)
__device__ __align__(128) float g_phi [(size_t)NROWS * DD];  // [m][k] tf32-rounded
__device__ __align__(128) float g_phiT[(size_t)DD * NROWS];  // [i][n] tf32-rounded
__device__ __align__(128) float g_Wr  [(size_t)DD * DD];     // W tf32-rounded (same layout)
__device__ __align__(128) float g_g   [(size_t)NROWS * DD];  // [n][j] tf32-rounded

// ---------------- helpers ----------------
__device__ __forceinline__ uint32_t s2u(const void* p) {
    uint32_t a;
    asm("{ .reg .u64 t; cvta.to.shared.u64 t, %1; cvt.u32.u64 %0, t; }" : "=r"(a) : "l"(p));
    return a;
}
__device__ __forceinline__ float tf32r(float x) {
    uint32_t u;
    asm("cvt.rna.tf32.f32 %0, %1;" : "=r"(u) : "f"(x));
    return __uint_as_float(u);
}
__device__ __forceinline__ float row_t(int m) {
    return fmaf(c_nodes[m % 15], 1.0f / 256.0f, (float)(2 * (m / 15) + 1) * (1.0f / 256.0f));
}
__device__ __forceinline__ float row_coef(int m) {
    return c_wk[m % 15] * (1.0f / 256.0f);
}
__device__ __forceinline__ void cp16(uint32_t dst, const float* src) {
    asm volatile("cp.async.cg.shared.global [%0], [%1], 16;" :: "r"(dst), "l"(src));
}
__device__ __forceinline__ void cp_commit() {
    asm volatile("cp.async.commit_group;" ::: "memory");
}
template<int N>
__device__ __forceinline__ void cp_wait() {
    asm volatile("cp.async.wait_group %0;" :: "n"(N) : "memory");
}
__device__ __forceinline__ void mma_tf32(float* d, const uint32_t* a, const uint32_t* b) {
    asm volatile(
        "mma.sync.aligned.m16n8k8.row.col.f32.tf32.tf32.f32 "
        "{%0,%1,%2,%3}, {%4,%5,%6,%7}, {%8,%9}, {%0,%1,%2,%3};"
        : "+f"(d[0]), "+f"(d[1]), "+f"(d[2]), "+f"(d[3])
        : "r"(a[0]), "r"(a[1]), "r"(a[2]), "r"(a[3]), "r"(b[0]), "r"(b[1]));
}

// ---------------- prep kernels ----------------
// phi[m][d] = rna_tf32(sin(t_m * freqs[d])), and phiT[d][m]
__global__ __launch_bounds__(256) void phi_gen(const float* __restrict__ freqs) {
    __shared__ float tile[32][33];
    const int d0 = blockIdx.x * 32, m0 = blockIdx.y * 32;
    const int tx = threadIdx.x, ty = threadIdx.y;
    float f = freqs[d0 + tx];
    #pragma unroll
    for (int r = 0; r < 4; r++) {
        int ml = ty + r * 8;
        int m = m0 + ml;
        float v = tf32r(sinf(row_t(m) * f));
        g_phi[(size_t)m * DD + d0 + tx] = v;
        tile[ml][tx] = v;
    }
    __syncthreads();
    #pragma unroll
    for (int r = 0; r < 4; r++) {
        int dl = ty + r * 8;
        g_phiT[(size_t)(d0 + dl) * NROWS + m0 + tx] = tile[tx][dl];
    }
}

// elementwise tf32 pre-round of W (same layout)
__global__ __launch_bounds__(256) void wr_gen(const float* __restrict__ W) {
    size_t i = ((size_t)blockIdx.x * 256 + threadIdx.x) * 4;
    float4 v = *reinterpret_cast<const float4*>(W + i);
    v.x = tf32r(v.x); v.y = tf32r(v.y); v.z = tf32r(v.z); v.w = tf32r(v.w);
    *reinterpret_cast<float4*>(g_Wr + i) = v;
}

// ---------------- pipelined tf32 mma GEMM ----------------
// C[M,N] = A[M,K](K-major) @ B[K,N](N-major rows)
// EPI1: fused bias + tanh' + cos*GK-weight epilogue, tf32-rounded store
template<int KTOT, bool EPI1>
__global__ void __launch_bounds__(NTHREADS, 2) gemm_mma(
    const float* __restrict__ gA, int ldA,
    const float* __restrict__ gB,
    const float* __restrict__ bias,
    const float* __restrict__ afreqs,
    float* __restrict__ outp)
{
    constexpr int KT = KTOT / BK;
    extern __shared__ float sm[];
    float* As = sm;                       // NSTAGE * A_STG
    float* Bs = sm + NSTAGE * A_STG;      // NSTAGE * B_STG

    const int tid = threadIdx.x;
    const int wid = tid >> 5, lane = tid & 31;
    const int wy = wid >> 2, wx = wid & 3;        // 2 x 4 warp grid
    const int r = lane >> 2, kq = lane & 3, gid = lane >> 2;
    const int bm = blockIdx.y * BM, bn = blockIdx.x * BN;

    float d[4][4][4];
    #pragma unroll
    for (int mt = 0; mt < 4; mt++)
        #pragma unroll
        for (int nt = 0; nt < 4; nt++)
            #pragma unroll
            for (int j = 0; j < 4; j++) d[mt][nt][j] = 0.0f;

    // ---- async stage loader ----
    auto load_stage = [&](int kt, int slot) {
        const int k0 = kt * BK;
        float* Asl = As + slot * A_STG;
        float* Bsl = Bs + slot * B_STG;
        // A: 128 rows x 4 chunks(16B) = 512 chunks; 2 per thread
        #pragma unroll
        for (int i = 0; i < 2; i++) {
            int c = tid + i * NTHREADS;
            int row = c >> 2, col = c & 3;
            cp16(s2u(Asl + row * ASTRIDE + col * 4),
                 gA + (size_t)(bm + row) * ldA + k0 + col * 4);
        }
        // B: 16 rows x 32 chunks = 512 chunks; 2 per thread
        #pragma unroll
        for (int i = 0; i < 2; i++) {
            int c = tid + i * NTHREADS;
            int row = c >> 5, col = c & 31;
            cp16(s2u(Bsl + row * BSTRIDE + col * 4),
                 gB + (size_t)(k0 + row) * DD + bn + col * 4);
        }
    };

    // prologue: stages 0..NSTAGE-2
    #pragma unroll
    for (int s = 0; s < NSTAGE - 1; s++) { load_stage(s, s); cp_commit(); }

    #pragma unroll 1
    for (int kt = 0; kt < KT; kt++) {
        cp_wait<NSTAGE - 2>();
        __syncthreads();
        // issue next stage (always commit to keep group accounting uniform)
        if (kt + NSTAGE - 1 < KT) load_stage(kt + NSTAGE - 1, (kt + NSTAGE - 1) & (NSTAGE - 1));
        cp_commit();

        const int slot = kt & (NSTAGE - 1);
        const float* Asl = As + slot * A_STG + (wy * 64) * ASTRIDE;
        const float* Bsl = Bs + slot * B_STG + wx * 32;

        #pragma unroll
        for (int kk = 0; kk < 2; kk++) {
            const int co = kk * 8;
            uint32_t bf[4][2];
            #pragma unroll
            for (int nt = 0; nt < 4; nt++) {
                int n = nt * 8 + gid;
                bf[nt][0] = __float_as_uint(Bsl[(co + kq)     * BSTRIDE + n]);
                bf[nt][1] = __float_as_uint(Bsl[(co + kq + 4) * BSTRIDE + n]);
            }
            #pragma unroll
            for (int mt = 0; mt < 4; mt++) {
                const float* ap = Asl + (mt * 16 + r) * ASTRIDE + co + kq;
                uint32_t af[4];
                af[0] = __float_as_uint(ap[0]);
                af[1] = __float_as_uint(ap[8 * ASTRIDE]);
                af[2] = __float_as_uint(ap[4]);
                af[3] = __float_as_uint(ap[8 * ASTRIDE + 4]);
                #pragma unroll
                for (int nt = 0; nt < 4; nt++) mma_tf32(d[mt][nt], af, bf[nt]);
            }
        }
    }

    // ---- epilogue ----
    #pragma unroll
    for (int mt = 0; mt < 4; mt++) {
        const int m0 = bm + wy * 64 + mt * 16 + r;
        #pragma unroll
        for (int h = 0; h < 2; h++) {
            const int m = m0 + h * 8;
            float t = 0.f, cf = 0.f;
            if (EPI1) { t = row_t(m); cf = row_coef(m); }
            #pragma unroll
            for (int nt = 0; nt < 4; nt++) {
                const int n = bn + wx * 32 + nt * 8 + 2 * kq;
                float v0 = d[mt][nt][2 * h], v1 = d[mt][nt][2 * h + 1];
                if (EPI1) {
                    float z0 = v0 + __ldg(bias + n);
                    float z1 = v1 + __ldg(bias + n + 1);
                    float t0 = tanhf(z0), t1 = tanhf(z1);
                    v0 = tf32r(cf * cosf(t * __ldg(afreqs + n))     * (1.0f - t0 * t0));
                    v1 = tf32r(cf * cosf(t * __ldg(afreqs + n + 1)) * (1.0f - t1 * t1));
                }
                *reinterpret_cast<float2*>(outp + (size_t)m * DD + n) = make_float2(v0, v1);
            }
        }
    }
}

// ---------------- host ----------------
extern "C" void kernel_launch(void* const* d_in, const int* in_sizes, int n_in,
                              void* d_out, int out_size) {
    const float* W      = (const float*)d_in[0];
    const float* bias   = (const float*)d_in[1];
    const float* freqs  = (const float*)d_in[2];
    const float* afreqs = (const float*)d_in[3];
    float* out = (float*)d_out;

    void* p_phi;  cudaGetSymbolAddress(&p_phi,  g_phi);
    void* p_phiT; cudaGetSymbolAddress(&p_phiT, g_phiT);
    void* p_Wr;   cudaGetSymbolAddress(&p_Wr,   g_Wr);
    void* p_g;    cudaGetSymbolAddress(&p_g,    g_g);

    // No static guards (harness rule): set attributes unconditionally; idempotent.
    cudaFuncSetAttribute(gemm_mma<DD, true>,     cudaFuncAttributeMaxDynamicSharedMemorySize, SMEM_BYTES);
    cudaFuncSetAttribute(gemm_mma<NROWS, false>, cudaFuncAttributeMaxDynamicSharedMemorySize, SMEM_BYTES);

    phi_gen<<<dim3(DD / 32, NROWS / 32), dim3(32, 8)>>>(freqs);
    wr_gen<<<(DD * DD) / (256 * 4), 256>>>(W);

    // GEMM1: z = phi @ W (+bias) -> g = coef*cos*(1-tanh^2)   [1920 x 4096]
    gemm_mma<DD, true><<<dim3(DD / BN, NROWS / BM), NTHREADS, SMEM_BYTES>>>(
        (const float*)p_phi, DD, (const float*)p_Wr, bias, afreqs, (float*)p_g);
    // GEMM2: out = phiT @ g   [4096 x 4096], K = 1920
    gemm_mma<NROWS, false><<<dim3(DD / BN, DD / BM), NTHREADS, SMEM_BYTES>>>(
        (const float*)p_phiT, NROWS, (const float*)p_g, bias, afreqs, out);

    (void)in_sizes; (void)n_in; (void)out_size;
}